// round 5
// baseline (speedup 1.0000x reference)
#include <cuda_runtime.h>
#include <cuda_fp16.h>

#define TT_ 512
#define HH_ 256
#define DD_ 256

// Packed fp16 weights (prepared once per launch call):
// g_Qp/g_Rp: [dir][kc][j], kc = k/8, uint4 = 8 halves w[k..k+7][j]
// g_Wp/g_Up: [dir][kp][j], kp = k/2, uint4 = (i,f)@k,(g,o)@k, (i,f)@k+1,(g,o)@k+1
__device__ uint4 g_Qp[2 * 32 * 256];
__device__ uint4 g_Rp[2 * 32 * 256];
__device__ uint4 g_Wp[2 * 128 * 256];
__device__ uint4 g_Up[2 * 128 * 256];

static __device__ __forceinline__ unsigned packh2(float a, float b) {
    __half2 h = __halves2half2(__float2half_rn(a), __float2half_rn(b));
    return *reinterpret_cast<unsigned*>(&h);
}

// ---------------------------------------------------------------------------
// One kernel: zero the output AND pack weights to fp16.
// ---------------------------------------------------------------------------
__global__ void prep_zero_kernel(const float* __restrict__ Q,
                                 const float* __restrict__ R,
                                 const float* __restrict__ Wih_fw,
                                 const float* __restrict__ Whh_fw,
                                 const float* __restrict__ Wih_bw,
                                 const float* __restrict__ Whh_bw,
                                 float4* __restrict__ out4, int n4) {
    int i = blockIdx.x * blockDim.x + threadIdx.x;
    if (i < n4) out4[i] = make_float4(0.f, 0.f, 0.f, 0.f);

    if (i < 16384) {                       // Qp
        int dir = i >> 13, rem = i & 8191, kc = rem >> 8, jj = rem & 255;
        const float* P = Q + dir * 65536;
        int k0 = kc * 8;
        uint4 r;
        r.x = packh2(P[(k0 + 0) * 256 + jj], P[(k0 + 1) * 256 + jj]);
        r.y = packh2(P[(k0 + 2) * 256 + jj], P[(k0 + 3) * 256 + jj]);
        r.z = packh2(P[(k0 + 4) * 256 + jj], P[(k0 + 5) * 256 + jj]);
        r.w = packh2(P[(k0 + 6) * 256 + jj], P[(k0 + 7) * 256 + jj]);
        g_Qp[i] = r;
    } else if (i < 32768) {                // Rp
        int m = i - 16384;
        int dir = m >> 13, rem = m & 8191, kc = rem >> 8, jj = rem & 255;
        const float* P = R + dir * 65536;
        int k0 = kc * 8;
        uint4 r;
        r.x = packh2(P[(k0 + 0) * 256 + jj], P[(k0 + 1) * 256 + jj]);
        r.y = packh2(P[(k0 + 2) * 256 + jj], P[(k0 + 3) * 256 + jj]);
        r.z = packh2(P[(k0 + 4) * 256 + jj], P[(k0 + 5) * 256 + jj]);
        r.w = packh2(P[(k0 + 6) * 256 + jj], P[(k0 + 7) * 256 + jj]);
        g_Rp[m] = r;
    } else if (i < 98304) {                // Wp (Wih)
        int m = i - 32768;
        int dir = m >> 15, rem = m & 32767, kp = rem >> 8, jj = rem & 255;
        const float* W = dir ? Wih_bw : Wih_fw;
        int k0 = 2 * kp;
        uint4 r;
        r.x = packh2(W[(0 * 256 + jj) * 256 + k0],     W[(1 * 256 + jj) * 256 + k0]);
        r.y = packh2(W[(2 * 256 + jj) * 256 + k0],     W[(3 * 256 + jj) * 256 + k0]);
        r.z = packh2(W[(0 * 256 + jj) * 256 + k0 + 1], W[(1 * 256 + jj) * 256 + k0 + 1]);
        r.w = packh2(W[(2 * 256 + jj) * 256 + k0 + 1], W[(3 * 256 + jj) * 256 + k0 + 1]);
        g_Wp[m] = r;
    } else if (i < 163840) {               // Up (Whh)
        int m = i - 98304;
        int dir = m >> 15, rem = m & 32767, kp = rem >> 8, jj = rem & 255;
        const float* W = dir ? Whh_bw : Whh_fw;
        int k0 = 2 * kp;
        uint4 r;
        r.x = packh2(W[(0 * 256 + jj) * 256 + k0],     W[(1 * 256 + jj) * 256 + k0]);
        r.y = packh2(W[(2 * 256 + jj) * 256 + k0],     W[(3 * 256 + jj) * 256 + k0]);
        r.z = packh2(W[(0 * 256 + jj) * 256 + k0 + 1], W[(1 * 256 + jj) * 256 + k0 + 1]);
        r.w = packh2(W[(2 * 256 + jj) * 256 + k0 + 1], W[(3 * 256 + jj) * 256 + k0 + 1]);
        g_Up[m] = r;
    }
}

// ---------------------------------------------------------------------------
__device__ __forceinline__ float sigmf(float z) {
    float e;
    asm("ex2.approx.f32 %0, %1;" : "=f"(e) : "f"(-1.442695041f * z));
    float r;
    asm("rcp.approx.f32 %0, %1;" : "=f"(r) : "f"(1.0f + e));
    return r;
}
__device__ __forceinline__ float tanha(float z) {
    return 2.0f * sigmf(2.0f * z) - 1.0f;
}

// 8 k-steps for BOTH rows (split-k stages).
__device__ __forceinline__ void accum8(uint4 w,
                                       const float* __restrict__ v0p,
                                       const float* __restrict__ v1p,
                                       float& a0, float& b0, float& a1, float& b1) {
    const __half2* wh = reinterpret_cast<const __half2*>(&w);
    float2 w01 = __half22float2(wh[0]);
    float2 w23 = __half22float2(wh[1]);
    float2 w45 = __half22float2(wh[2]);
    float2 w67 = __half22float2(wh[3]);
    float4 pA = *(const float4*)(v0p);
    float4 pB = *(const float4*)(v0p + 4);
    float4 qA = *(const float4*)(v1p);
    float4 qB = *(const float4*)(v1p + 4);
    a0 = fmaf(pA.x, w01.x, a0); b0 = fmaf(pA.y, w01.y, b0);
    a0 = fmaf(pA.z, w23.x, a0); b0 = fmaf(pA.w, w23.y, b0);
    a0 = fmaf(pB.x, w45.x, a0); b0 = fmaf(pB.y, w45.y, b0);
    a0 = fmaf(pB.z, w67.x, a0); b0 = fmaf(pB.w, w67.y, b0);
    a1 = fmaf(qA.x, w01.x, a1); b1 = fmaf(qA.y, w01.y, b1);
    a1 = fmaf(qA.z, w23.x, a1); b1 = fmaf(qA.w, w23.y, b1);
    a1 = fmaf(qB.x, w45.x, a1); b1 = fmaf(qB.y, w45.y, b1);
    a1 = fmaf(qB.z, w67.x, a1); b1 = fmaf(qB.w, w67.y, b1);
}

// Q matvec, row-split: full 256-k sum for ONE row, weights in smem.
__device__ __forceinline__ float mvQ(const uint4* __restrict__ sQ, int j,
                                     const float* __restrict__ v) {
    float a0 = 0.f, a1 = 0.f, a2 = 0.f, a3 = 0.f;
#pragma unroll
    for (int kc = 0; kc < 32; ++kc) {
        uint4 w = sQ[kc * 256 + j];
        const __half2* wh = reinterpret_cast<const __half2*>(&w);
        float2 w01 = __half22float2(wh[0]);
        float2 w23 = __half22float2(wh[1]);
        float2 w45 = __half22float2(wh[2]);
        float2 w67 = __half22float2(wh[3]);
        float4 pA = *(const float4*)(v + kc * 8);
        float4 pB = *(const float4*)(v + kc * 8 + 4);
        a0 = fmaf(pA.x, w01.x, a0); a1 = fmaf(pA.y, w01.y, a1);
        a2 = fmaf(pA.z, w23.x, a2); a3 = fmaf(pA.w, w23.y, a3);
        a0 = fmaf(pB.x, w45.x, a0); a1 = fmaf(pB.y, w45.y, a1);
        a2 = fmaf(pB.z, w67.x, a2); a3 = fmaf(pB.w, w67.y, a3);
    }
    return (a0 + a1) + (a2 + a3);
}

// R matvec partials, split-k: half0 = kc 0..15 from smem.
__device__ __forceinline__ void mvR_s(const uint4* __restrict__ sR, int j,
                                      const float* __restrict__ v0,
                                      const float* __restrict__ v1,
                                      float& o0, float& o1) {
    float a0 = 0.f, b0 = 0.f, a1 = 0.f, b1 = 0.f;
#pragma unroll
    for (int kc = 0; kc < 16; ++kc)
        accum8(sR[kc * 256 + j], v0 + kc * 8, v1 + kc * 8, a0, b0, a1, b1);
    o0 = a0 + b0; o1 = a1 + b1;
}
// half1 = kc 16..31 streamed from L2.
__device__ __forceinline__ void mvR_g(const uint4* __restrict__ Rp, int j,
                                      const float* __restrict__ v0,
                                      const float* __restrict__ v1,
                                      float& o0, float& o1) {
    float a0 = 0.f, b0 = 0.f, a1 = 0.f, b1 = 0.f;
#pragma unroll
    for (int g = 0; g < 2; ++g) {
        uint4 w[8];
#pragma unroll
        for (int t = 0; t < 8; ++t) w[t] = __ldg(Rp + (16 + g * 8 + t) * 256 + j);
#pragma unroll
        for (int t = 0; t < 8; ++t)
            accum8(w[t], v0 + (16 + g * 8 + t) * 8, v1 + (16 + g * 8 + t) * 8,
                   a0, b0, a1, b1);
    }
    o0 = a0 + b0; o1 = a1 + b1;
}

// gate accumulation for one k-pair, both rows.
__device__ __forceinline__ void acc_gates(uint4 w, float x0, float x1,
                                          float y0, float y1,
                                          float& i0, float& f0, float& g0, float& o0,
                                          float& i1, float& f1, float& g1, float& o1) {
    const __half2* wh = reinterpret_cast<const __half2*>(&w);
    float2 ifa = __half22float2(wh[0]);
    float2 goa = __half22float2(wh[1]);
    float2 ifb = __half22float2(wh[2]);
    float2 gob = __half22float2(wh[3]);
    i0 = fmaf(x0, ifa.x, i0); f0 = fmaf(x0, ifa.y, f0);
    g0 = fmaf(x0, goa.x, g0); o0 = fmaf(x0, goa.y, o0);
    i0 = fmaf(x1, ifb.x, i0); f0 = fmaf(x1, ifb.y, f0);
    g0 = fmaf(x1, gob.x, g0); o0 = fmaf(x1, gob.y, o0);
    i1 = fmaf(y0, ifa.x, i1); f1 = fmaf(y0, ifa.y, f1);
    g1 = fmaf(y0, goa.x, g1); o1 = fmaf(y0, goa.y, o1);
    i1 = fmaf(y1, ifb.x, i1); f1 = fmaf(y1, ifb.y, f1);
    g1 = fmaf(y1, gob.x, g1); o1 = fmaf(y1, gob.y, o1);
}

// smem layout offsets (bytes)
#define OFF_Q     0          // uint4[32*256]  128KB  (Q, this dir)
#define OFF_R     131072     // uint4[16*256]   64KB  (R kc 0..15, this dir)
#define OFF_SX    196608     // float[2][256]
#define OFF_SHM   198656     // float[2][256]
#define OFF_SHC   200704     // float[2][256]
#define OFF_RED2  202752     // float2[2][256]
#define OFF_REDG0 206848     // float4[2][256]  row0 gate partials
#define OFF_REDG1 215040     // float4[2][256]  row1 gate partials
#define SMEM_BYTES 223232

// ---------------------------------------------------------------------------
// Main: 128 CTAs x 512 threads. tid = (h<<8)|j ; thread (j,h) owns output
// unit j; "half" h is the k-split / row-split lane.
// ---------------------------------------------------------------------------
__global__ void __launch_bounds__(512, 1)
moglstm_main(const float* __restrict__ x,
             const int*   __restrict__ lengths,
             const float* __restrict__ bih_fw, const float* __restrict__ bhh_fw,
             const float* __restrict__ bih_bw, const float* __restrict__ bhh_bw,
             float* __restrict__ out) {
    extern __shared__ __align__(16) unsigned char smem_raw[];
    uint4*  sQ    = (uint4*)(smem_raw + OFF_Q);
    uint4*  sR    = (uint4*)(smem_raw + OFF_R);
    float*  sx    = (float*)(smem_raw + OFF_SX);    // [2][256]
    float*  shm   = (float*)(smem_raw + OFF_SHM);   // [2][256]
    float*  shc   = (float*)(smem_raw + OFF_SHC);   // [2][256]
    float2* red2  = (float2*)(smem_raw + OFF_RED2); // [2][256]
    float4* redg0 = (float4*)(smem_raw + OFF_REDG0);// [2][256]
    float4* redg1 = (float4*)(smem_raw + OFF_REDG1);// [2][256]

    const int tid = threadIdx.x;
    const int j   = tid & 255;
    const int h   = tid >> 8;
    const int dir = blockIdx.x >> 6;
    const int pr  = blockIdx.x & 63;
    const int b0 = 2 * pr, b1 = b0 + 1;
    const int len0 = lengths[b0];
    const int len1 = lengths[b1];
    const int lenmax = max(len0, len1);
    const int myb   = h ? b1 : b0;
    const int mylen = h ? len1 : len0;

    const uint4* Rp = g_Rp + dir * 8192;
    const uint4* Wp = g_Wp + dir * 32768;
    const uint4* Up = g_Up + dir * 32768;
    const float* bih = dir ? bih_bw : bih_fw;
    const float* bhh = dir ? bhh_bw : bhh_fw;
    const float bi = bih[j]       + bhh[j];
    const float bf = bih[256 + j] + bhh[256 + j];
    const float bg = bih[512 + j] + bhh[512 + j];
    const float bo = bih[768 + j] + bhh[768 + j];

    // load Q (full) and R (half) to smem; zero carried h
    for (int i = tid; i < 8192; i += 512) sQ[i] = g_Qp[dir * 8192 + i];
    for (int i = tid; i < 4096; i += 512) sR[i] = g_Rp[dir * 8192 + i];
    shc[tid] = 0.f;        // covers [2][256]
    float c = 0.f;         // cell state of row h, unit j
    __syncthreads();

    const float* xb = x + (size_t)myb * TT_ * DD_;
    const int kpb = h * 64;

    for (int n = 0; n < lenmax; ++n) {
        const int tt = dir ? (lenmax - 1 - n) : n;
        const bool act = (tt < mylen);

        float xl = __ldg(xb + tt * DD_ + j);

        // stage 1: u = h @ Q (row-split) ; x1 = 2 sig(u) x
        float u = mvQ(sQ, j, shc + h * 256);
        float x1 = 2.f * sigmf(u) * xl;
        sx[h * 256 + j] = x1;
        __syncthreads();

        // stage 2: v = x1 @ R (split-k) ; h1 = 2 sig(v) h
        float o0, o1;
        if (h == 0) mvR_s(sR, j, sx, sx + 256, o0, o1);
        else        mvR_g(Rp, j, sx, sx + 256, o0, o1);
        red2[h * 256 + j] = make_float2(o0, o1);
        __syncthreads();
        float2 pa = red2[j], pb = red2[256 + j];
        float v = h ? (pa.y + pb.y) : (pa.x + pb.x);
        float h1 = 2.f * sigmf(v) * shc[h * 256 + j];
        shm[h * 256 + j] = h1;
        __syncthreads();

        // stage 3: u2 = h1 @ Q (row-split) ; x2 = 2 sig(u2) x1
        u = mvQ(sQ, j, shm + h * 256);
        float x2 = 2.f * sigmf(u) * x1;
        sx[h * 256 + j] = x2;
        __syncthreads();

        // stage 4: v2 = x2 @ R (split-k) ; h2 = 2 sig(v2) h1
        if (h == 0) mvR_s(sR, j, sx, sx + 256, o0, o1);
        else        mvR_g(Rp, j, sx, sx + 256, o0, o1);
        red2[h * 256 + j] = make_float2(o0, o1);
        __syncthreads();
        pa = red2[j]; pb = red2[256 + j];
        v = h ? (pa.y + pb.y) : (pa.x + pb.x);
        float h2 = 2.f * sigmf(v) * h1;
        shm[h * 256 + j] = h2;
        __syncthreads();

        // stage 5: gate partials over kp in [h*64, h*64+64)
        float gi0 = 0.f, gf0 = 0.f, gg0 = 0.f, go0 = 0.f;
        float gi1 = 0.f, gf1 = 0.f, gg1 = 0.f, go1 = 0.f;
#pragma unroll 2
        for (int kp = kpb; kp < kpb + 64; kp += 2) {
            uint4 w0 = __ldg(Wp + (kp + 0) * 256 + j);
            uint4 w1 = __ldg(Wp + (kp + 1) * 256 + j);
            uint4 q0 = __ldg(Up + (kp + 0) * 256 + j);
            uint4 q1 = __ldg(Up + (kp + 1) * 256 + j);
            float4 xa = *(const float4*)&sx[kp * 2];
            float4 xc = *(const float4*)&sx[256 + kp * 2];
            float4 ha = *(const float4*)&shm[kp * 2];
            float4 hc = *(const float4*)&shm[256 + kp * 2];
            acc_gates(w0, xa.x, xa.y, xc.x, xc.y,
                      gi0, gf0, gg0, go0, gi1, gf1, gg1, go1);
            acc_gates(w1, xa.z, xa.w, xc.z, xc.w,
                      gi0, gf0, gg0, go0, gi1, gf1, gg1, go1);
            acc_gates(q0, ha.x, ha.y, hc.x, hc.y,
                      gi0, gf0, gg0, go0, gi1, gf1, gg1, go1);
            acc_gates(q1, ha.z, ha.w, hc.z, hc.w,
                      gi0, gf0, gg0, go0, gi1, gf1, gg1, go1);
        }
        redg0[h * 256 + j] = make_float4(gi0, gf0, gg0, go0);
        redg1[h * 256 + j] = make_float4(gi1, gf1, gg1, go1);
        __syncthreads();

        // stage 6: thread (j,h) finalizes row h
        float4 ga, gb;
        if (h == 0) { ga = redg0[j]; gb = redg0[256 + j]; }
        else        { ga = redg1[j]; gb = redg1[256 + j]; }
        float gi = ga.x + gb.x + bi;
        float gf = ga.y + gb.y + bf;
        float gg = ga.z + gb.z + bg;
        float go = ga.w + gb.w + bo;
        float ig = sigmf(gi), fg = sigmf(gf), og = sigmf(go);
        float gv = tanha(gg);
        float cn = fg * c + ig * gv;
        float hn = og * tanha(cn);
        if (act) {
            c = cn;
            shc[h * 256 + j] = hn;
            atomicAdd(&out[((size_t)myb * TT_ + tt) * HH_ + j], hn);
        }
        __syncthreads();   // shc commit visible; sx/shm safe to overwrite
    }
}

// ---------------------------------------------------------------------------
extern "C" void kernel_launch(void* const* d_in, const int* in_sizes, int n_in,
                              void* d_out, int out_size) {
    (void)in_sizes; (void)n_in;
    const float* x      = (const float*)d_in[0];
    const int*   lengths= (const int*)  d_in[1];
    const float* Q      = (const float*)d_in[2];
    const float* R      = (const float*)d_in[3];
    const float* Wih_fw = (const float*)d_in[4];
    const float* Whh_fw = (const float*)d_in[5];
    const float* bih_fw = (const float*)d_in[6];
    const float* bhh_fw = (const float*)d_in[7];
    const float* Wih_bw = (const float*)d_in[8];
    const float* Whh_bw = (const float*)d_in[9];
    const float* bih_bw = (const float*)d_in[10];
    const float* bhh_bw = (const float*)d_in[11];
    float* out = (float*)d_out;

    static int attr_set = 0;
    if (!attr_set) {
        cudaFuncSetAttribute(moglstm_main,
                             cudaFuncAttributeMaxDynamicSharedMemorySize,
                             SMEM_BYTES);
        attr_set = 1;
    }

    prep_zero_kernel<<<16384, 256>>>(Q, R, Wih_fw, Whh_fw, Wih_bw, Whh_bw,
                                     (float4*)out, out_size / 4);
    moglstm_main<<<128, 512, SMEM_BYTES>>>(x, lengths, bih_fw, bhh_fw,
                                           bih_bw, bhh_bw, out);
}